// round 6
// baseline (speedup 1.0000x reference)
#include <cuda_runtime.h>
#include <cstdint>

// Thin-plate spline (order 3), 1024x1024 grid, batch 4 (all batches identical).
//   out[b,y,x] = sum_m ((x-tx_m)^2 + (y-ty_m)^2)^{3/2} * ww_m/2^40 + v0*x + v1*y + v2
//
// R6: R5 issued ~28K redundant LDGs per block (unrolled __ldg of the same 35
// constants from 514+1024 threads) -> front-batched MLP_p1~48 -> cross-CTA
// L1tex-queue contention (spr_max ~2x per B300 model). Constants are now
// staged into SMEM once per block (~35 LDGs); phase 1/2 read SMEM broadcast.
// Coarse stride-4 RBF grid + bilinear interp (rel_err 6.3e-8, budget 1e-3);
// stores leave via 4x 16KB cp.async.bulk per block.

#define WDIM 1024
#define HDIM 1024
#define MPTS 16
#define CC   257                      // coarse cols: x = 0,4,...,1024
#define RPB  4                        // rows per block
#define TILE_BYTES (RPB * WDIM * 4)   // 16 KB per batch plane

__device__ __forceinline__ float sqrt_approx(float v) {
    float r;
    asm("sqrt.approx.f32 %0, %1;" : "=f"(r) : "f"(v));
    return r;
}

__device__ __forceinline__ uint32_t smem_u32(const void* p) {
    uint32_t a;
    asm("{ .reg .u64 t; cvta.to.shared.u64 t, %1; cvt.u32.u64 %0, t; }"
        : "=r"(a) : "l"(p));
    return a;
}

__global__ void __launch_bounds__(1024, 2) spline_kernel(
    const float* __restrict__ train_points,  // [16,2] in [0,1]
    const float* __restrict__ ww,            // [16]
    const float* __restrict__ vw,            // [3]
    float* __restrict__ out,                 // [B, 1024, 1024]
    int B)
{
    __shared__ float4 tile[RPB * WDIM / 4];  // 16 KB: 4 rows x 1024 px
    __shared__ float  g[2][CC];              // coarse RBF rows at y0, y0+4
    __shared__ float  stx[MPTS], sty[MPTS], sw[MPTS], sv[3];

    const int t  = threadIdx.x;
    const int y0 = blockIdx.x << 2;          // stripe rows y0..y0+3

    // ---- phase 0: stage constants into SMEM (one LDG each) ----
    if (t < MPTS) {
        stx[t] = train_points[2 * t]     * 1024.0f;
        sty[t] = train_points[2 * t + 1] * 1024.0f;
        sw[t]  = ww[t] * (1.0f / 1099511627776.0f);   // ww * 2^-40
    } else if (t < MPTS + 3) {
        sv[t - MPTS] = vw[t - MPTS];
    }
    __syncthreads();

    // ---- phase 1: coarse RBF samples (x stride 4; rows y0 and y0+4) ----
    if (t < 2 * CC) {
        const int row = (t >= CC) ? 1 : 0;
        const int col = t - row * CC;
        const float fx = (float)(col << 2);
        const float fy = (float)(y0 + (row << 2));
        float acc = 0.0f;
#pragma unroll
        for (int m = 0; m < MPTS; ++m) {
            const float dx = fx - stx[m];
            const float dy = fy - sty[m];
            const float r2 = fmaf(dx, dx, dy * dy);
            acc = fmaf(r2 * sw[m], sqrt_approx(r2), acc);   // + w * r2^{3/2}
        }
        g[row][col] = acc;
    }
    __syncthreads();

    // ---- phase 2: bilinear interp + exact linear term -> smem tile ----
    {
        const int r    = t >> 8;         // 0..3: row within stripe
        const int lane = t & 255;        // coarse cell = x0/4
        const int y    = y0 + r;
        const int x0   = lane << 2;
        const float fyf = 0.25f * (float)r;

        const float gT0 = g[0][lane];
        const float gT1 = g[0][lane + 1];
        const float gB0 = g[1][lane];
        const float gB1 = g[1][lane + 1];

        const float gL = fmaf(gB0 - gT0, fyf, gT0);   // rbf at (x0,   y)
        const float gR = fmaf(gB1 - gT1, fyf, gT1);   // rbf at (x0+4, y)
        const float dg = (gR - gL) * 0.25f;           // rbf x-slope per pixel

        const float v0 = sv[0], v1 = sv[1], v2 = sv[2];
        const float base  = gL + fmaf((float)y, v1, v2) + (float)x0 * v0;
        const float slope = dg + v0;

        float4 v;
        v.x = base;
        v.y = base + slope;
        v.z = fmaf(slope, 2.0f, base);
        v.w = fmaf(slope, 3.0f, base);

        tile[t] = v;   // (r*1024 + x0)/4 == t -> conflict-free STS.128
    }
    __syncthreads();

    // ---- phase 3: bulk-async stores, one 16KB copy per batch plane ----
    if (t == 0) {
        asm volatile("fence.proxy.async.shared::cta;" ::: "memory");
        const uint32_t src = smem_u32(tile);
        const size_t plane = (size_t)WDIM * HDIM;
        float* dst0 = out + (size_t)y0 * WDIM;
#pragma unroll 4
        for (int b = 0; b < B; ++b) {
            asm volatile(
                "cp.async.bulk.global.shared::cta.bulk_group [%0], [%1], %2;"
                :: "l"(dst0 + b * plane), "r"(src), "n"(TILE_BYTES)
                : "memory");
        }
        asm volatile("cp.async.bulk.commit_group;" ::: "memory");
        asm volatile("cp.async.bulk.wait_group 0;" ::: "memory");
    }
}

extern "C" void kernel_launch(void* const* d_in, const int* in_sizes, int n_in,
                              void* d_out, int out_size)
{
    // inputs: x [B,1024,1024,1] (shape only), train_points [1,16,2],
    //         ww [1,16,1], vw [1,3,1]
    const float* train_points = (const float*)d_in[1];
    const float* ww           = (const float*)d_in[2];
    const float* vw           = (const float*)d_in[3];
    float* out = (float*)d_out;

    const int B = in_sizes[0] / (WDIM * HDIM);  // = 4

    dim3 grid(HDIM / RPB);    // 256 blocks, one per 4-row stripe -> one wave
    dim3 block(1024);
    spline_kernel<<<grid, block>>>(train_points, ww, vw, out, B);
}

// round 7
// speedup vs baseline: 1.0036x; 1.0036x over previous
#include <cuda_runtime.h>
#include <cstdint>

// Thin-plate spline (order 3), 1024x1024 grid, batch 4 (all batches identical).
//   out[b,y,x] = sum_m ((x-tx_m)^2 + (y-ty_m)^2)^{3/2} * ww_m/2^40 + v0*x + v1*y + v2
//
// R7: barrier-free, warp-autonomous. Evidence R1-R6: no pipe >26%, time stuck
// at 6.5-7.5us regardless of math/store path => the wall was the serialized
// per-block critical path (3 barriers + block-held tails). Now each warp owns
// 256 px of one row, computes its own 18 coarse RBF samples (stride-32 grid,
// interp err ~7e-7 rel, budget 1e-3) in lanes 0..17, shares via shuffles,
// interpolates, and stores 2 float4 x 4 batches. No smem, no syncthreads,
// no TMA wait. 512 blocks x 256 threads.

#define WDIM 1024
#define HDIM 1024
#define MPTS 16

__device__ __forceinline__ float sqrt_approx(float v) {
    float r;
    asm("sqrt.approx.f32 %0, %1;" : "=f"(r) : "f"(v));
    return r;
}

__global__ void __launch_bounds__(256) spline_kernel(
    const float* __restrict__ tp,   // [16,2] in [0,1]
    const float* __restrict__ ww,   // [16]
    const float* __restrict__ vw,   // [3]
    float* __restrict__ out,        // [B, 1024, 1024]
    int B)
{
    const int gtid = blockIdx.x * 256 + threadIdx.x;
    const int warp = gtid >> 5;           // 0..4095
    const int lane = gtid & 31;
    const int y    = warp >> 2;           // 0..1023 (4 warps per row)
    const int x0w  = (warp & 3) << 8;     // 256-px segment origin

    // ---- coarse RBF sample for this lane (lanes 0..17 carry real samples) --
    // samples: x = x0w + {0,32,...,256} (9), y = fy0 and fy0+32
    const int   srow = (lane >= 9) ? 1 : 0;
    const int   sidx = srow ? (lane - 9) : lane;
    const int   fy0i = y & ~31;
    const float fx = (float)(x0w + (sidx << 5));
    const float fy = (float)(fy0i + (srow << 5));

    float acc = 0.0f;
#pragma unroll
    for (int m = 0; m < MPTS; ++m) {
        const float tx = __ldg(&tp[2 * m])     * 1024.0f;
        const float ty = __ldg(&tp[2 * m + 1]) * 1024.0f;
        const float w  = __ldg(&ww[m]) * (1.0f / 1099511627776.0f); // *2^-40
        const float dx = fx - tx;
        const float dy = fy - ty;
        const float r2 = fmaf(dx, dx, dy * dy);
        acc = fmaf(r2 * w, sqrt_approx(r2), acc);   // + w * r2^{3/2}
    }

    // ---- share samples, bilinear interp ------------------------------------
    // lane handles float4 #lane (px xa..xa+3) and #(lane+32) (px xa+128..)
    const unsigned FULL = 0xffffffffu;
    const int ca = lane >> 3;      // coarse cell of first quad  (0..3)
    const int cb = ca + 4;         // coarse cell of second quad (4..7)

    const float Ta0 = __shfl_sync(FULL, acc, ca);
    const float Ta1 = __shfl_sync(FULL, acc, ca + 1);
    const float Ba0 = __shfl_sync(FULL, acc, 9 + ca);
    const float Ba1 = __shfl_sync(FULL, acc, 9 + ca + 1);
    const float Tb0 = __shfl_sync(FULL, acc, cb);
    const float Tb1 = __shfl_sync(FULL, acc, cb + 1);
    const float Bb0 = __shfl_sync(FULL, acc, 9 + cb);
    const float Bb1 = __shfl_sync(FULL, acc, 9 + cb + 1);

    const float fyf = (float)(y - fy0i) * (1.0f / 32.0f);
    const float gLa = fmaf(Ba0 - Ta0, fyf, Ta0);
    const float gRa = fmaf(Ba1 - Ta1, fyf, Ta1);
    const float gLb = fmaf(Bb0 - Tb0, fyf, Tb0);
    const float gRb = fmaf(Bb1 - Tb1, fyf, Tb1);

    const float v0 = __ldg(&vw[0]);
    const float v1 = __ldg(&vw[1]);
    const float v2 = __ldg(&vw[2]);

    const int xa = x0w + (lane << 2);
    const int xb = xa + 128;
    const float fa   = (float)(xa & 31) * (1.0f / 32.0f); // frac at quad start
    const float liny = fmaf((float)y, v1, v2);

    const float sa = fmaf(gRa - gLa, 1.0f / 32.0f, v0);   // per-px slope
    const float sb = fmaf(gRb - gLb, 1.0f / 32.0f, v0);
    const float ba = fmaf(gRa - gLa, fa, gLa) + liny + (float)xa * v0;
    const float bb = fmaf(gRb - gLb, fa, gLb) + liny + (float)xb * v0;

    float4 qa, qb;
    qa.x = ba;            qa.y = ba + sa;
    qa.z = fmaf(sa, 2.0f, ba); qa.w = fmaf(sa, 3.0f, ba);
    qb.x = bb;            qb.y = bb + sb;
    qb.z = fmaf(sb, 2.0f, bb); qb.w = fmaf(sb, 3.0f, bb);

    // ---- stores: coalesced float4, 4 batches -------------------------------
    const size_t offa  = (size_t)y * WDIM + xa;
    const size_t plane = (size_t)WDIM * HDIM;
#pragma unroll 4
    for (int b = 0; b < B; ++b) {
        float* p = out + b * plane + offa;
        *reinterpret_cast<float4*>(p)       = qa;
        *reinterpret_cast<float4*>(p + 128) = qb;
    }
}

extern "C" void kernel_launch(void* const* d_in, const int* in_sizes, int n_in,
                              void* d_out, int out_size)
{
    // inputs: x [B,1024,1024,1] (shape only), train_points [1,16,2],
    //         ww [1,16,1], vw [1,3,1]
    const float* train_points = (const float*)d_in[1];
    const float* ww           = (const float*)d_in[2];
    const float* vw           = (const float*)d_in[3];
    float* out = (float*)d_out;

    const int B = in_sizes[0] / (WDIM * HDIM);  // = 4

    // 4096 warps: 1024 rows x 4 segments; 8 warps per 256-thread block
    spline_kernel<<<512, 256>>>(train_points, ww, vw, out, B);
}